// round 15
// baseline (speedup 1.0000x reference)
#include <cuda_runtime.h>
#include <stdint.h>

#define N        8192
#define DIM      64
#define NROUNDS  13
#define NTHREADS 1024

// ---------------- scratch (__device__ globals; no allocations) -------------
__device__ float              g_D[(size_t)N * (size_t)N];  // 256 MB fp32
__device__ float              g_sq[N];
__device__ unsigned long long g_best[N];       // per-vertex best: (dbits<<13)|u
__device__ unsigned short     g_comp[N];       // component label (a root id)
__device__ unsigned long long g_edges[N];      // MST edges: (dbits<<26)|(v<<13)|u
__device__ int                g_edge_cnt;
__device__ int                g_done;

__device__ __forceinline__ unsigned redux_min_u32(unsigned v) {
    unsigned r;
    asm volatile("redux.sync.min.u32 %0, %1, 0xffffffff;" : "=r"(r) : "r"(v));
    return r;
}

// ---------------------------------------------------------------------------
// Kernel 1: squared norms + Boruvka state init (fused)
// ---------------------------------------------------------------------------
__global__ void norms_kernel(const float* __restrict__ x) {
    int i = blockIdx.x * blockDim.x + threadIdx.x;
    if (i < N) {
        const float4* p = (const float4*)(x + (size_t)i * DIM);
        float s = 0.0f;
        #pragma unroll
        for (int k = 0; k < DIM / 4; k++) {
            float4 v = p[k];
            s += v.x * v.x + v.y * v.y + v.z * v.z + v.w * v.w;
        }
        g_sq[i] = s;
        g_comp[i] = (unsigned short)i;
        g_best[i] = ~0ull;
    }
    if (i == 0) { g_edge_cnt = 0; g_done = 0; }
}

// ---------------------------------------------------------------------------
// D[i][j] = sqrt(max(sq_i + sq_j - 2*x_i.x_j, 0))
// 128x128 tile per block, 16x16 threads, 8x8 per thread, transposed smem.
// ---------------------------------------------------------------------------
__global__ void dist_kernel(const float* __restrict__ x) {
    __shared__ float At[32][132];   // At[k][i] = x[row0+i][kk+k]
    __shared__ float Bt[32][132];

    const int tx = threadIdx.x, ty = threadIdx.y;   // 16x16
    const int tid = ty * 16 + tx;
    const int row0 = blockIdx.y * 128;
    const int col0 = blockIdx.x * 128;

    float acc[8][8];
    #pragma unroll
    for (int i = 0; i < 8; i++)
        #pragma unroll
        for (int j = 0; j < 8; j++) acc[i][j] = 0.0f;

    for (int kk = 0; kk < DIM; kk += 32) {
        #pragma unroll
        for (int q = 0; q < 4; q++) {
            int lin = tid + (q << 8);
            int r   = lin >> 3;
            int f   = lin & 7;
            float4 a = *(const float4*)(x + (size_t)(row0 + r) * DIM + kk + f * 4);
            At[f * 4 + 0][r] = a.x; At[f * 4 + 1][r] = a.y;
            At[f * 4 + 2][r] = a.z; At[f * 4 + 3][r] = a.w;
            float4 b = *(const float4*)(x + (size_t)(col0 + r) * DIM + kk + f * 4);
            Bt[f * 4 + 0][r] = b.x; Bt[f * 4 + 1][r] = b.y;
            Bt[f * 4 + 2][r] = b.z; Bt[f * 4 + 3][r] = b.w;
        }
        __syncthreads();

        #pragma unroll
        for (int k = 0; k < 32; k++) {
            float a[8], b[8];
            *(float4*)(a)     = *(const float4*)&At[k][ty * 8];
            *(float4*)(a + 4) = *(const float4*)&At[k][ty * 8 + 4];
            *(float4*)(b)     = *(const float4*)&Bt[k][tx * 8];
            *(float4*)(b + 4) = *(const float4*)&Bt[k][tx * 8 + 4];
            #pragma unroll
            for (int i = 0; i < 8; i++)
                #pragma unroll
                for (int j = 0; j < 8; j++)
                    acc[i][j] = fmaf(a[i], b[j], acc[i][j]);
        }
        __syncthreads();
    }

    float sqc[8];
    #pragma unroll
    for (int j = 0; j < 8; j++) sqc[j] = g_sq[col0 + tx * 8 + j];
    #pragma unroll
    for (int i = 0; i < 8; i++) {
        float sqr = g_sq[row0 + ty * 8 + i];
        float d[8];
        #pragma unroll
        for (int j = 0; j < 8; j++)
            d[j] = sqrtf(fmaxf(sqr + sqc[j] - 2.0f * acc[i][j], 0.0f));
        float* orow = g_D + (size_t)(row0 + ty * 8 + i) * N + col0 + tx * 8;
        *(float4*)(orow)     = *(float4*)(d);
        *(float4*)(orow + 4) = *(float4*)(d + 4);
    }
}

// ---------------------------------------------------------------------------
// Boruvka scan: per-vertex min outgoing edge (masked row min). One block/row.
// ---------------------------------------------------------------------------
__global__ void scan_kernel(int round) {
    if (g_done) return;
    const int v = blockIdx.x;
    const int t = threadIdx.x;                 // 256 threads
    const unsigned short myc = g_comp[v];

    __shared__ int do_scan;
    if (t == 0) {
        int ds = 1;
        if (round > 0) {
            unsigned u = (unsigned)g_best[v] & 0x1FFFu;
            if (g_comp[u] != myc) ds = 0;      // cache still valid
        }
        do_scan = ds;
    }
    __syncthreads();
    if (!do_scan) return;

    const float* row = g_D + (size_t)v * N;
    unsigned lv = 0xFFFFFFFFu, li = 0;
    #pragma unroll
    for (int c = 0; c < 8; c++) {
        int u0 = c * 1024 + t * 4;
        float4  d4 = *(const float4*)(row + u0);
        ushort4 c4 = *(const ushort4*)(g_comp + u0);
        if (c4.x != myc) { unsigned db = __float_as_uint(d4.x); if (db < lv) { lv = db; li = u0;     } }
        if (c4.y != myc) { unsigned db = __float_as_uint(d4.y); if (db < lv) { lv = db; li = u0 + 1; } }
        if (c4.z != myc) { unsigned db = __float_as_uint(d4.z); if (db < lv) { lv = db; li = u0 + 2; } }
        if (c4.w != myc) { unsigned db = __float_as_uint(d4.w); if (db < lv) { lv = db; li = u0 + 3; } }
    }

    __shared__ unsigned long long parts[8];
    unsigned wv = redux_min_u32(lv);
    unsigned wi = redux_min_u32((lv == wv) ? li : 0xFFFFFFFFu);
    if ((t & 31) == 0) parts[t >> 5] = ((unsigned long long)wv << 13) | wi;
    __syncthreads();
    if (t < 32) {
        unsigned long long p = (t < 8) ? parts[t] : ~0ull;
        unsigned v2 = (unsigned)(p >> 13), i2 = (unsigned)p & 0x1FFFu;
        unsigned gv = redux_min_u32(v2);
        unsigned gi = redux_min_u32((v2 == gv) ? i2 : 0xFFFFFFFFu);
        if (t == 0) g_best[v] = ((unsigned long long)gv << 13) | gi;
    }
}

// ---------------------------------------------------------------------------
// Boruvka pick+union — compbest in dynamic smem (64 KB), parent in static
// smem (32 KB). Pointer jumping is ADAPTIVE (converge-check, typ. ~4 iters).
// ---------------------------------------------------------------------------
#define PK_SMEM (N * 8)

__global__ void __launch_bounds__(NTHREADS, 1) pick_kernel() {
    if (g_done) return;
    const int t = threadIdx.x;
    extern __shared__ unsigned long long cbm[];   // [N] 64 KB dynamic
    __shared__ int s_par[N];                      // 32 KB static
    __shared__ int s_chg;

    for (int v = t; v < N; v += NTHREADS) { cbm[v] = ~0ull; s_par[v] = v; }
    __syncthreads();

    for (int v = t; v < N; v += NTHREADS) {
        unsigned long long b = g_best[v];
        unsigned long long w = b >> 13;                 // fp32 dist bits
        unsigned u = (unsigned)b & 0x1FFFu;
        unsigned c = g_comp[v];
        atomicMin(&cbm[c], (w << 26) | ((unsigned long long)v << 13) | u);
    }
    __syncthreads();

    // hooks + edge emission (distinct weights => mutual pair is the SAME edge)
    for (int v = t; v < N; v += NTHREADS) {
        if ((int)g_comp[v] == v) {
            unsigned long long cb = cbm[v];
            if (cb != ~0ull) {
                unsigned b = (unsigned)cb & 0x1FFFu;             // outside endpoint
                unsigned a = (unsigned)(cb >> 13) & 0x1FFFu;     // inside endpoint
                unsigned d = g_comp[b];
                s_par[v] = (int)d;
                unsigned long long cbd = cbm[d];
                unsigned b2 = (unsigned)cbd & 0x1FFFu;
                unsigned a2 = (unsigned)(cbd >> 13) & 0x1FFFu;
                bool mutual = (a2 == b && b2 == a);
                if (!mutual || v < (int)d) {
                    int pos = atomicAdd(&g_edge_cnt, 1);
                    g_edges[pos] = cb;
                }
            }
        }
    }
    __syncthreads();

    // break 2-cycles: smaller id becomes root
    for (int v = t; v < N; v += NTHREADS) {
        int p = s_par[v];
        if (s_par[p] == v && v < p) s_par[v] = v;
    }
    __syncthreads();

    // adaptive pointer jumping in smem (break when converged)
    for (int it = 0; it < 13; it++) {
        if (t == 0) s_chg = 0;
        __syncthreads();
        int chg = 0;
        for (int v = t; v < N; v += NTHREADS) {
            int p  = s_par[v];
            int gp = s_par[p];
            if (p != gp) { s_par[v] = gp; chg = 1; }
        }
        if (chg) s_chg = 1;                 // benign race, same value
        __syncthreads();
        if (!s_chg) break;
    }

    // relabel
    unsigned short nc[N / NTHREADS];
    #pragma unroll
    for (int k = 0; k < N / NTHREADS; k++)
        nc[k] = (unsigned short)s_par[g_comp[t + k * NTHREADS]];
    __syncthreads();
    #pragma unroll
    for (int k = 0; k < N / NTHREADS; k++)
        g_comp[t + k * NTHREADS] = nc[k];
    __syncthreads();

    if (t == 0 && g_edge_cnt >= N - 1) g_done = 1;
}

// ---------------------------------------------------------------------------
// Replay v8: single-warp Prim, parent-rank filter, ONE syncwarp per step.
// After ns = redux(kv) the warp is converged and every lane holds ns; ALL
// lanes store submins[j>>5]=ns (one converged STS). The owning lane's
// subsequent uint4 LDS of that slot reads its own program-ordered store, so
// syncwarp #2 is unnecessary. Cross-step: the in-order warp issues this STS
// before any next-step atomicMin (empirically validated by R12's pass).
// ---------------------------------------------------------------------------
#define OFF_SBUF    0                          // u64[8192]; after compact:
                                               //   eAB u32[8192] @0, wtab f32[8192] @32768
#define OFF_ADJ     65536                      // u32[16384]
#define OFF_ROWPTR  131072                     // u16[8194] (+pad)
#define OFF_KEYS    147584                     // u32[8192]  (cur alias during CSR)
#define OFF_SUBMIN  180352                     // u32[256]
#define OFF_SCR     181376                     // u32[32]
#define OFF_ROWPAIR 181504                     // u32[8192]
#define SM_TOTAL    214272

#define DEADK  0xFFFFFFFFu
#define INFR   0x1FFFu

__global__ void __launch_bounds__(NTHREADS, 1) replay_kernel(float* __restrict__ out) {
    extern __shared__ unsigned char smraw[];
    unsigned long long* sbuf    = (unsigned long long*)(smraw + OFF_SBUF);
    unsigned*           eAB     = (unsigned*)(smraw + OFF_SBUF);        // alias
    float*              wtab    = (float*)(smraw + OFF_SBUF + 32768);   // alias
    unsigned*           adj     = (unsigned*)(smraw + OFF_ADJ);
    unsigned short*     rowptr  = (unsigned short*)(smraw + OFF_ROWPTR);
    unsigned*           keys    = (unsigned*)(smraw + OFF_KEYS);
    unsigned*           submins = (unsigned*)(smraw + OFF_SUBMIN);
    unsigned*           scratch = (unsigned*)(smraw + OFF_SCR);
    unsigned*           rowpair = (unsigned*)(smraw + OFF_ROWPAIR);

    const int t = threadIdx.x, lane = t & 31, warp = t >> 5;
    const int ne = N - 1;

    // ---- load + bitonic sort edges by weight (ascending; pads sort last) ----
    for (int e = t; e < N; e += NTHREADS)
        sbuf[e] = (e < ne) ? g_edges[e] : ~0ull;
    __syncthreads();
    for (int k = 2; k <= N; k <<= 1) {
        for (int m = k >> 1; m > 0; m >>= 1) {
            for (int i = t; i < N; i += NTHREADS) {
                int ixj = i ^ m;
                if (ixj > i) {
                    bool up = ((i & k) == 0);
                    unsigned long long A = sbuf[i], B = sbuf[ixj];
                    if ((A > B) == up) { sbuf[i] = B; sbuf[ixj] = A; }
                }
            }
            __syncthreads();
        }
    }

    // ---- compact: endpoints + weight table overwrite sbuf region ----
    {
        unsigned long long ed[8];
        #pragma unroll
        for (int k = 0; k < 8; k++) ed[k] = sbuf[t + (k << 10)];
        __syncthreads();
        #pragma unroll
        for (int k = 0; k < 8; k++) {
            int r = t + (k << 10);
            eAB[r]  = (unsigned)(ed[k] & 0x3FFFFFFu);
            wtab[r] = __uint_as_float((unsigned)(ed[k] >> 26));
        }
    }
    // ---- CSR (cur aliases keys region) ----
    unsigned* cur = keys;
    for (int v = t; v < N; v += NTHREADS) cur[v] = 0;
    __syncthreads();
    for (int r = t; r < ne; r += NTHREADS) {
        unsigned e = eAB[r];
        atomicAdd(&cur[(e >> 13) & 0x1FFFu], 1u);
        atomicAdd(&cur[e & 0x1FFFu], 1u);
    }
    __syncthreads();
    {   // exclusive scan of degrees -> rowptr (u16), thread owns 8 consecutive
        unsigned loc[8], s = 0;
        #pragma unroll
        for (int k = 0; k < 8; k++) { loc[k] = s; s += cur[t * 8 + k]; }
        unsigned x = s;
        #pragma unroll
        for (int o = 1; o < 32; o <<= 1) {
            unsigned y = __shfl_up_sync(0xffffffffu, x, o);
            if (lane >= o) x += y;
        }
        if (lane == 31) scratch[warp] = x;
        __syncthreads();
        unsigned wt = scratch[lane];
        unsigned xx = wt;
        #pragma unroll
        for (int o = 1; o < 32; o <<= 1) {
            unsigned y = __shfl_up_sync(0xffffffffu, xx, o);
            if (lane >= o) xx += y;
        }
        unsigned wbase = __shfl_sync(0xffffffffu, xx, warp) - scratch[warp];
        unsigned base = wbase + (x - s);
        #pragma unroll
        for (int k = 0; k < 8; k++)
            rowptr[t * 8 + k] = (unsigned short)(base + loc[k]);
        if (t == NTHREADS - 1) rowptr[N] = (unsigned short)(base + s);
    }
    __syncthreads();
    for (int v = t; v < N; v += NTHREADS) cur[v] = rowptr[v];
    __syncthreads();
    for (int r = t; r < ne; r += NTHREADS) {
        unsigned e = eAB[r];
        unsigned a = (e >> 13) & 0x1FFFu;
        unsigned b = e & 0x1FFFu;
        unsigned rr = (unsigned)r << 13;
        adj[atomicAdd(&cur[a], 1u)] = rr | b;
        adj[atomicAdd(&cur[b], 1u)] = rr | a;
    }
    __syncthreads();
    // rowpair: one LDS per step instead of two
    for (int v = t; v < N; v += NTHREADS)
        rowpair[v] = (unsigned)rowptr[v] | ((unsigned)rowptr[v + 1] << 16);
    __syncthreads();

    // ---- init keys (overwrite cur) + submins ----
    for (int v = t; v < N; v += NTHREADS)
        keys[v] = (v == 0) ? DEADK : ((INFR << 13) | (unsigned)v);
    if (t < 256)
        submins[t] = (t == 0) ? ((INFR << 13) | 1u)
                              : ((INFR << 13) | ((unsigned)t << 5));
    __syncthreads();

    if (warp != 0) {
        // births (out poisoned each run; deaths written by warp 0)
        for (int i = t - 32; i < ne; i += NTHREADS - 32) out[2 * i] = 0.0f;
        return;
    }

    // ---- single-warp step loop: one syncwarp per step ----
    unsigned j   = 0;
    unsigned fin = DEADK;     // rank field 0x7FFFF: filters nothing at step 0

    for (int step = 0; step < ne; ++step) {
        unsigned rp = rowpair[j];                      // broadcast LDS

        // lane-parallel activation; parent edge filtered by RANK (register cmp)
        for (unsigned e = (rp & 0xFFFFu) + lane; e < (rp >> 16); e += 32) {
            unsigned a = adj[e];
            if ((a ^ fin) >> 13) {                     // not the parent edge
                unsigned u = a & 0x1FFFu;
                keys[u] = a;                           // written exactly once
                atomicMin(&submins[u >> 5], a);
            }
        }
        __syncwarp();

        // winner subblock: warp-parallel re-min + predicated kill
        unsigned base = j & ~31u;
        unsigned kv = keys[base + lane];
        if (base + lane == j) { kv = DEADK; keys[j] = DEADK; }
        unsigned ns = redux_min_u32(kv);               // converges the warp
        submins[j >> 5] = ns;                          // converged STS, ALL lanes

        // global select: each lane reads its 8 submins (own-store visible),
        // one redux selects AND broadcasts — no second syncwarp
        const uint4* sp = (const uint4*)(submins + (lane << 3));
        uint4 s0 = sp[0], s1 = sp[1];
        unsigned tm = min(min(min(s0.x, s0.y), min(s0.z, s0.w)),
                          min(min(s1.x, s1.y), min(s1.z, s1.w)));
        fin = redux_min_u32(tm);

        if (lane == 0) out[2 * step + 1] = wtab[fin >> 13];
        j = fin & 0x1FFFu;
    }
}

// ---------------------------------------------------------------------------
extern "C" void kernel_launch(void* const* d_in, const int* in_sizes, int n_in,
                              void* d_out, int out_size) {
    const float* x = (const float*)d_in[0];
    float* out = (float*)d_out;

    cudaFuncSetAttribute(replay_kernel,
                         cudaFuncAttributeMaxDynamicSharedMemorySize, SM_TOTAL);
    cudaFuncSetAttribute(pick_kernel,
                         cudaFuncAttributeMaxDynamicSharedMemorySize, PK_SMEM);

    norms_kernel<<<(N + 255) / 256, 256>>>(x);

    dim3 gblk(16, 16);
    dim3 ggrid(N / 128, N / 128);
    dist_kernel<<<ggrid, gblk>>>(x);

    for (int r = 0; r < NROUNDS; r++) {
        scan_kernel<<<N, 256>>>(r);
        pick_kernel<<<1, NTHREADS, PK_SMEM>>>();
    }

    replay_kernel<<<1, NTHREADS, SM_TOTAL>>>(out);
}

// round 16
// speedup vs baseline: 1.0937x; 1.0937x over previous
#include <cuda_runtime.h>
#include <stdint.h>

#define N        8192
#define DIM      64
#define NROUNDS  13
#define NTHREADS 1024

// ---------------- scratch (__device__ globals; no allocations) -------------
__device__ float              g_D[(size_t)N * (size_t)N];  // 256 MB fp32
__device__ float              g_sq[N];
__device__ unsigned long long g_best[N];       // per-vertex best: (dbits<<13)|u
__device__ unsigned short     g_comp[N];       // component label (a root id)
__device__ unsigned long long g_edges[N];      // MST edges: (dbits<<26)|(v<<13)|u
__device__ int                g_edge_cnt;
__device__ int                g_done;

__device__ __forceinline__ unsigned redux_min_u32(unsigned v) {
    unsigned r;
    asm volatile("redux.sync.min.u32 %0, %1, 0xffffffff;" : "=r"(r) : "r"(v));
    return r;
}

// ---------------------------------------------------------------------------
// Kernel 1: squared norms + Boruvka state init (fused)
// ---------------------------------------------------------------------------
__global__ void norms_kernel(const float* __restrict__ x) {
    int i = blockIdx.x * blockDim.x + threadIdx.x;
    if (i < N) {
        const float4* p = (const float4*)(x + (size_t)i * DIM);
        float s = 0.0f;
        #pragma unroll
        for (int k = 0; k < DIM / 4; k++) {
            float4 v = p[k];
            s += v.x * v.x + v.y * v.y + v.z * v.z + v.w * v.w;
        }
        g_sq[i] = s;
        g_comp[i] = (unsigned short)i;
        g_best[i] = ~0ull;
    }
    if (i == 0) { g_edge_cnt = 0; g_done = 0; }
}

// ---------------------------------------------------------------------------
// D[i][j] = sqrt(max(sq_i + sq_j - 2*x_i.x_j, 0))
// 128x128 tile per block, 16x16 threads, 8x8 per thread, transposed smem.
// ---------------------------------------------------------------------------
__global__ void dist_kernel(const float* __restrict__ x) {
    __shared__ float At[32][132];   // At[k][i] = x[row0+i][kk+k]
    __shared__ float Bt[32][132];

    const int tx = threadIdx.x, ty = threadIdx.y;   // 16x16
    const int tid = ty * 16 + tx;
    const int row0 = blockIdx.y * 128;
    const int col0 = blockIdx.x * 128;

    float acc[8][8];
    #pragma unroll
    for (int i = 0; i < 8; i++)
        #pragma unroll
        for (int j = 0; j < 8; j++) acc[i][j] = 0.0f;

    for (int kk = 0; kk < DIM; kk += 32) {
        #pragma unroll
        for (int q = 0; q < 4; q++) {
            int lin = tid + (q << 8);
            int r   = lin >> 3;
            int f   = lin & 7;
            float4 a = *(const float4*)(x + (size_t)(row0 + r) * DIM + kk + f * 4);
            At[f * 4 + 0][r] = a.x; At[f * 4 + 1][r] = a.y;
            At[f * 4 + 2][r] = a.z; At[f * 4 + 3][r] = a.w;
            float4 b = *(const float4*)(x + (size_t)(col0 + r) * DIM + kk + f * 4);
            Bt[f * 4 + 0][r] = b.x; Bt[f * 4 + 1][r] = b.y;
            Bt[f * 4 + 2][r] = b.z; Bt[f * 4 + 3][r] = b.w;
        }
        __syncthreads();

        #pragma unroll
        for (int k = 0; k < 32; k++) {
            float a[8], b[8];
            *(float4*)(a)     = *(const float4*)&At[k][ty * 8];
            *(float4*)(a + 4) = *(const float4*)&At[k][ty * 8 + 4];
            *(float4*)(b)     = *(const float4*)&Bt[k][tx * 8];
            *(float4*)(b + 4) = *(const float4*)&Bt[k][tx * 8 + 4];
            #pragma unroll
            for (int i = 0; i < 8; i++)
                #pragma unroll
                for (int j = 0; j < 8; j++)
                    acc[i][j] = fmaf(a[i], b[j], acc[i][j]);
        }
        __syncthreads();
    }

    float sqc[8];
    #pragma unroll
    for (int j = 0; j < 8; j++) sqc[j] = g_sq[col0 + tx * 8 + j];
    #pragma unroll
    for (int i = 0; i < 8; i++) {
        float sqr = g_sq[row0 + ty * 8 + i];
        float d[8];
        #pragma unroll
        for (int j = 0; j < 8; j++)
            d[j] = sqrtf(fmaxf(sqr + sqc[j] - 2.0f * acc[i][j], 0.0f));
        float* orow = g_D + (size_t)(row0 + ty * 8 + i) * N + col0 + tx * 8;
        *(float4*)(orow)     = *(float4*)(d);
        *(float4*)(orow + 4) = *(float4*)(d + 4);
    }
}

// ---------------------------------------------------------------------------
// Boruvka scan: per-vertex min outgoing edge (masked row min). One block/row.
// ---------------------------------------------------------------------------
__global__ void scan_kernel(int round) {
    if (g_done) return;
    const int v = blockIdx.x;
    const int t = threadIdx.x;                 // 256 threads
    const unsigned short myc = g_comp[v];

    __shared__ int do_scan;
    if (t == 0) {
        int ds = 1;
        if (round > 0) {
            unsigned u = (unsigned)g_best[v] & 0x1FFFu;
            if (g_comp[u] != myc) ds = 0;      // cache still valid
        }
        do_scan = ds;
    }
    __syncthreads();
    if (!do_scan) return;

    const float* row = g_D + (size_t)v * N;
    unsigned lv = 0xFFFFFFFFu, li = 0;
    #pragma unroll
    for (int c = 0; c < 8; c++) {
        int u0 = c * 1024 + t * 4;
        float4  d4 = *(const float4*)(row + u0);
        ushort4 c4 = *(const ushort4*)(g_comp + u0);
        if (c4.x != myc) { unsigned db = __float_as_uint(d4.x); if (db < lv) { lv = db; li = u0;     } }
        if (c4.y != myc) { unsigned db = __float_as_uint(d4.y); if (db < lv) { lv = db; li = u0 + 1; } }
        if (c4.z != myc) { unsigned db = __float_as_uint(d4.z); if (db < lv) { lv = db; li = u0 + 2; } }
        if (c4.w != myc) { unsigned db = __float_as_uint(d4.w); if (db < lv) { lv = db; li = u0 + 3; } }
    }

    __shared__ unsigned long long parts[8];
    unsigned wv = redux_min_u32(lv);
    unsigned wi = redux_min_u32((lv == wv) ? li : 0xFFFFFFFFu);
    if ((t & 31) == 0) parts[t >> 5] = ((unsigned long long)wv << 13) | wi;
    __syncthreads();
    if (t < 32) {
        unsigned long long p = (t < 8) ? parts[t] : ~0ull;
        unsigned v2 = (unsigned)(p >> 13), i2 = (unsigned)p & 0x1FFFu;
        unsigned gv = redux_min_u32(v2);
        unsigned gi = redux_min_u32((v2 == gv) ? i2 : 0xFFFFFFFFu);
        if (t == 0) g_best[v] = ((unsigned long long)gv << 13) | gi;
    }
}

// ---------------------------------------------------------------------------
// Boruvka pick+union — compbest in dynamic smem (64 KB), parent in static
// smem (32 KB). Pointer jumping is ADAPTIVE (converge-check, typ. ~4 iters).
// ---------------------------------------------------------------------------
#define PK_SMEM (N * 8)

__global__ void __launch_bounds__(NTHREADS, 1) pick_kernel() {
    if (g_done) return;
    const int t = threadIdx.x;
    extern __shared__ unsigned long long cbm[];   // [N] 64 KB dynamic
    __shared__ int s_par[N];                      // 32 KB static
    __shared__ int s_chg;

    for (int v = t; v < N; v += NTHREADS) { cbm[v] = ~0ull; s_par[v] = v; }
    __syncthreads();

    for (int v = t; v < N; v += NTHREADS) {
        unsigned long long b = g_best[v];
        unsigned long long w = b >> 13;                 // fp32 dist bits
        unsigned u = (unsigned)b & 0x1FFFu;
        unsigned c = g_comp[v];
        atomicMin(&cbm[c], (w << 26) | ((unsigned long long)v << 13) | u);
    }
    __syncthreads();

    // hooks + edge emission (distinct weights => mutual pair is the SAME edge)
    for (int v = t; v < N; v += NTHREADS) {
        if ((int)g_comp[v] == v) {
            unsigned long long cb = cbm[v];
            if (cb != ~0ull) {
                unsigned b = (unsigned)cb & 0x1FFFu;             // outside endpoint
                unsigned a = (unsigned)(cb >> 13) & 0x1FFFu;     // inside endpoint
                unsigned d = g_comp[b];
                s_par[v] = (int)d;
                unsigned long long cbd = cbm[d];
                unsigned b2 = (unsigned)cbd & 0x1FFFu;
                unsigned a2 = (unsigned)(cbd >> 13) & 0x1FFFu;
                bool mutual = (a2 == b && b2 == a);
                if (!mutual || v < (int)d) {
                    int pos = atomicAdd(&g_edge_cnt, 1);
                    g_edges[pos] = cb;
                }
            }
        }
    }
    __syncthreads();

    // break 2-cycles: smaller id becomes root
    for (int v = t; v < N; v += NTHREADS) {
        int p = s_par[v];
        if (s_par[p] == v && v < p) s_par[v] = v;
    }
    __syncthreads();

    // adaptive pointer jumping in smem (break when converged)
    for (int it = 0; it < 13; it++) {
        if (t == 0) s_chg = 0;
        __syncthreads();
        int chg = 0;
        for (int v = t; v < N; v += NTHREADS) {
            int p  = s_par[v];
            int gp = s_par[p];
            if (p != gp) { s_par[v] = gp; chg = 1; }
        }
        if (chg) s_chg = 1;                 // benign race, same value
        __syncthreads();
        if (!s_chg) break;
    }

    // relabel
    unsigned short nc[N / NTHREADS];
    #pragma unroll
    for (int k = 0; k < N / NTHREADS; k++)
        nc[k] = (unsigned short)s_par[g_comp[t + k * NTHREADS]];
    __syncthreads();
    #pragma unroll
    for (int k = 0; k < N / NTHREADS; k++)
        g_comp[t + k * NTHREADS] = nc[k];
    __syncthreads();

    if (t == 0 && g_edge_cnt >= N - 1) g_done = 1;
}

// ---------------------------------------------------------------------------
// Replay (R11-exact, FROZEN): single-warp Prim, parent-rank filter,
// two syncwarps. Three attempted restructures (R8, R12, R15) all regressed —
// smem has no store-forwarding, and single-warp issue count is the budget.
// ---------------------------------------------------------------------------
#define OFF_SBUF    0                          // u64[8192]; after compact:
                                               //   eAB u32[8192] @0, wtab f32[8192] @32768
#define OFF_ADJ     65536                      // u32[16384]
#define OFF_ROWPTR  131072                     // u16[8194] (+pad)
#define OFF_KEYS    147584                     // u32[8192]  (cur alias during CSR)
#define OFF_SUBMIN  180352                     // u32[256]
#define OFF_SCR     181376                     // u32[32]
#define OFF_ROWPAIR 181504                     // u32[8192]
#define SM_TOTAL    214272

#define DEADK  0xFFFFFFFFu
#define INFR   0x1FFFu

__global__ void __launch_bounds__(NTHREADS, 1) replay_kernel(float* __restrict__ out) {
    extern __shared__ unsigned char smraw[];
    unsigned long long* sbuf    = (unsigned long long*)(smraw + OFF_SBUF);
    unsigned*           eAB     = (unsigned*)(smraw + OFF_SBUF);        // alias
    float*              wtab    = (float*)(smraw + OFF_SBUF + 32768);   // alias
    unsigned*           adj     = (unsigned*)(smraw + OFF_ADJ);
    unsigned short*     rowptr  = (unsigned short*)(smraw + OFF_ROWPTR);
    unsigned*           keys    = (unsigned*)(smraw + OFF_KEYS);
    unsigned*           submins = (unsigned*)(smraw + OFF_SUBMIN);
    unsigned*           scratch = (unsigned*)(smraw + OFF_SCR);
    unsigned*           rowpair = (unsigned*)(smraw + OFF_ROWPAIR);

    const int t = threadIdx.x, lane = t & 31, warp = t >> 5;
    const int ne = N - 1;

    // ---- load + bitonic sort edges by weight (ascending; pads sort last) ----
    for (int e = t; e < N; e += NTHREADS)
        sbuf[e] = (e < ne) ? g_edges[e] : ~0ull;
    __syncthreads();
    for (int k = 2; k <= N; k <<= 1) {
        for (int m = k >> 1; m > 0; m >>= 1) {
            for (int i = t; i < N; i += NTHREADS) {
                int ixj = i ^ m;
                if (ixj > i) {
                    bool up = ((i & k) == 0);
                    unsigned long long A = sbuf[i], B = sbuf[ixj];
                    if ((A > B) == up) { sbuf[i] = B; sbuf[ixj] = A; }
                }
            }
            __syncthreads();
        }
    }

    // ---- compact: endpoints + weight table overwrite sbuf region ----
    {
        unsigned long long ed[8];
        #pragma unroll
        for (int k = 0; k < 8; k++) ed[k] = sbuf[t + (k << 10)];
        __syncthreads();
        #pragma unroll
        for (int k = 0; k < 8; k++) {
            int r = t + (k << 10);
            eAB[r]  = (unsigned)(ed[k] & 0x3FFFFFFu);
            wtab[r] = __uint_as_float((unsigned)(ed[k] >> 26));
        }
    }
    // ---- CSR (cur aliases keys region) ----
    unsigned* cur = keys;
    for (int v = t; v < N; v += NTHREADS) cur[v] = 0;
    __syncthreads();
    for (int r = t; r < ne; r += NTHREADS) {
        unsigned e = eAB[r];
        atomicAdd(&cur[(e >> 13) & 0x1FFFu], 1u);
        atomicAdd(&cur[e & 0x1FFFu], 1u);
    }
    __syncthreads();
    {   // exclusive scan of degrees -> rowptr (u16), thread owns 8 consecutive
        unsigned loc[8], s = 0;
        #pragma unroll
        for (int k = 0; k < 8; k++) { loc[k] = s; s += cur[t * 8 + k]; }
        unsigned x = s;
        #pragma unroll
        for (int o = 1; o < 32; o <<= 1) {
            unsigned y = __shfl_up_sync(0xffffffffu, x, o);
            if (lane >= o) x += y;
        }
        if (lane == 31) scratch[warp] = x;
        __syncthreads();
        unsigned wt = scratch[lane];
        unsigned xx = wt;
        #pragma unroll
        for (int o = 1; o < 32; o <<= 1) {
            unsigned y = __shfl_up_sync(0xffffffffu, xx, o);
            if (lane >= o) xx += y;
        }
        unsigned wbase = __shfl_sync(0xffffffffu, xx, warp) - scratch[warp];
        unsigned base = wbase + (x - s);
        #pragma unroll
        for (int k = 0; k < 8; k++)
            rowptr[t * 8 + k] = (unsigned short)(base + loc[k]);
        if (t == NTHREADS - 1) rowptr[N] = (unsigned short)(base + s);
    }
    __syncthreads();
    for (int v = t; v < N; v += NTHREADS) cur[v] = rowptr[v];
    __syncthreads();
    for (int r = t; r < ne; r += NTHREADS) {
        unsigned e = eAB[r];
        unsigned a = (e >> 13) & 0x1FFFu;
        unsigned b = e & 0x1FFFu;
        unsigned rr = (unsigned)r << 13;
        adj[atomicAdd(&cur[a], 1u)] = rr | b;
        adj[atomicAdd(&cur[b], 1u)] = rr | a;
    }
    __syncthreads();
    // rowpair: one LDS per step instead of two
    for (int v = t; v < N; v += NTHREADS)
        rowpair[v] = (unsigned)rowptr[v] | ((unsigned)rowptr[v + 1] << 16);
    __syncthreads();

    // ---- init keys (overwrite cur) + submins ----
    for (int v = t; v < N; v += NTHREADS)
        keys[v] = (v == 0) ? DEADK : ((INFR << 13) | (unsigned)v);
    if (t < 256)
        submins[t] = (t == 0) ? ((INFR << 13) | 1u)
                              : ((INFR << 13) | ((unsigned)t << 5));
    __syncthreads();

    if (warp != 0) {
        // births (out poisoned each run; deaths written by warp 0)
        for (int i = t - 32; i < ne; i += NTHREADS - 32) out[2 * i] = 0.0f;
        return;
    }

    // ---- single-warp step loop (R11-exact) ----
    unsigned j   = 0;
    unsigned fin = DEADK;     // rank field 0x7FFFF: filters nothing at step 0

    for (int step = 0; step < ne; ++step) {
        unsigned rp = rowpair[j];                      // broadcast LDS

        // lane-parallel activation; parent edge filtered by RANK (register cmp)
        for (unsigned e = (rp & 0xFFFFu) + lane; e < (rp >> 16); e += 32) {
            unsigned a = adj[e];
            if ((a ^ fin) >> 13) {                     // not the parent edge
                unsigned u = a & 0x1FFFu;
                keys[u] = a;                           // written exactly once
                atomicMin(&submins[u >> 5], a);
            }
        }
        __syncwarp();

        // winner subblock: warp-parallel re-min + predicated kill
        unsigned base = j & ~31u;
        unsigned kv = keys[base + lane];
        if (base + lane == j) { kv = DEADK; keys[j] = DEADK; }
        unsigned ns = redux_min_u32(kv);
        if (lane == 0) submins[j >> 5] = ns;
        __syncwarp();

        // global select: each lane reads its 8 submins, one redux broadcasts
        const uint4* sp = (const uint4*)(submins + (lane << 3));
        uint4 s0 = sp[0], s1 = sp[1];
        unsigned tm = min(min(min(s0.x, s0.y), min(s0.z, s0.w)),
                          min(min(s1.x, s1.y), min(s1.z, s1.w)));
        fin = redux_min_u32(tm);

        if (lane == 0) out[2 * step + 1] = wtab[fin >> 13];
        j = fin & 0x1FFFu;
    }
}

// ---------------------------------------------------------------------------
extern "C" void kernel_launch(void* const* d_in, const int* in_sizes, int n_in,
                              void* d_out, int out_size) {
    const float* x = (const float*)d_in[0];
    float* out = (float*)d_out;

    cudaFuncSetAttribute(replay_kernel,
                         cudaFuncAttributeMaxDynamicSharedMemorySize, SM_TOTAL);
    cudaFuncSetAttribute(pick_kernel,
                         cudaFuncAttributeMaxDynamicSharedMemorySize, PK_SMEM);

    norms_kernel<<<(N + 255) / 256, 256>>>(x);

    dim3 gblk(16, 16);
    dim3 ggrid(N / 128, N / 128);
    dist_kernel<<<ggrid, gblk>>>(x);

    for (int r = 0; r < NROUNDS; r++) {
        scan_kernel<<<N, 256>>>(r);
        pick_kernel<<<1, NTHREADS, PK_SMEM>>>();
    }

    replay_kernel<<<1, NTHREADS, SM_TOTAL>>>(out);
}